// round 13
// baseline (speedup 1.0000x reference)
#include <cuda_runtime.h>
#include <cuda_bf16.h>
#include <cuda_fp16.h>
#include <cstdint>

#define N_NODES 100000
#define N_EDGES 1600000
#define D_IN    256
#define D_OUT   128

#define SCAN_BLOCK 1024
#define N_SCAN_BLOCKS ((N_NODES + SCAN_BLOCK - 1) / SCAN_BLOCK)   // 98

typedef unsigned long long ull;

// Device scratch (static __device__ arrays only; no allocation anywhere).
// g_count is loader-zero-initialized and re-zeroed by scan1 on every call,
// so hist always sees zeros (invariant maintained across calls/replays).
__device__ __half g_supph[(size_t)N_NODES * D_OUT];    // 25.6 MB fp16 support
__device__ int   g_count[N_NODES];
__device__ int   g_offsets[N_NODES + 1];
__device__ int   g_cursor[N_NODES];
__device__ int   g_bsum[N_SCAN_BLOCKS];
__device__ __align__(16) int2 g_sw[N_EDGES];           // packed (src, bits(w)), 16B-aligned

// ---------------------------------------------------------------------------
// helpers
// ---------------------------------------------------------------------------
__device__ __forceinline__ uint32_t f2tf32(float f) {
    uint32_t r;
    asm("cvt.rna.tf32.f32 %0, %1;" : "=r"(r) : "f"(f));
    return r;
}

__device__ __forceinline__ void mma_tf32(float& d0, float& d1, float& d2, float& d3,
                                         uint32_t a0, uint32_t a1, uint32_t a2, uint32_t a3,
                                         uint32_t b0, uint32_t b1) {
    asm volatile(
        "mma.sync.aligned.m16n8k8.row.col.f32.tf32.tf32.f32 "
        "{%0,%1,%2,%3}, {%4,%5,%6,%7}, {%8,%9}, {%0,%1,%2,%3};"
        : "+f"(d0), "+f"(d1), "+f"(d2), "+f"(d3)
        : "r"(a0), "r"(a1), "r"(a2), "r"(a3), "r"(b0), "r"(b1));
}

// Streaming (evict-first) 16B index load: edge list is read exactly once.
__device__ __forceinline__ int4 ldg_cs(const int4* p) {
    int4 v;
    asm("ld.global.cs.v4.b32 {%0,%1,%2,%3}, [%4];"
        : "=r"(v.x), "=r"(v.y), "=r"(v.z), "=r"(v.w) : "l"(p));
    return v;
}
// Streaming (evict-first) 16B store: out is written once, never re-read.
// Keeps the support working set resident in L2 instead of being evicted
// by write-allocate traffic.
__device__ __forceinline__ void stg_cs(float4* p, float4 v) {
    asm volatile("st.global.cs.v4.f32 [%0], {%1,%2,%3,%4};"
                 :: "l"(p), "f"(v.x), "f"(v.y), "f"(v.z), "f"(v.w) : "memory");
}

// ---------------------------------------------------------------------------
// GEMM: support = x @ W via tf32 mma. BM=128, BN=128, BK=16.
// 256 threads = 8 warps in 4(M) x 2(N): 32x64 per warp, 32 mmas per barrier.
// A stride 20 / B stride 136: fragment LDS conflict-free.
// ---------------------------------------------------------------------------
__global__ __launch_bounds__(256) void gemm_tf32_kernel(const float* __restrict__ x,
                                                        const float* __restrict__ W) {
    __shared__ uint32_t As[2][128][20];
    __shared__ uint32_t Bs[2][16][136];

    const int tid  = threadIdx.x;
    const int wid  = tid >> 5;
    const int lane = tid & 31;
    const int gid  = lane >> 2;
    const int tig  = lane & 3;
    const int warp_m = wid & 3;
    const int warp_n = wid >> 2;
    const int block_row = blockIdx.x * 128;

    const int lr = tid >> 1;
    const int lk = (tid & 1) * 8;
    const int bk = tid >> 5;
    const int bc = (tid & 31) * 4;

    const int grow = block_row + lr;
    const bool arow_ok = (grow < N_NODES);
    const float* xrow = x + (size_t)grow * D_IN;

    float acc[2][8][4];
#pragma unroll
    for (int mi = 0; mi < 2; ++mi)
#pragma unroll
        for (int ni = 0; ni < 8; ++ni)
#pragma unroll
            for (int c = 0; c < 4; ++c) acc[mi][ni][c] = 0.0f;

    auto stage = [&](int b, float4 a0, float4 a1, float4 w0, float4 w1) {
        uint4 t0 = make_uint4(f2tf32(a0.x), f2tf32(a0.y), f2tf32(a0.z), f2tf32(a0.w));
        uint4 t1 = make_uint4(f2tf32(a1.x), f2tf32(a1.y), f2tf32(a1.z), f2tf32(a1.w));
        *(uint4*)&As[b][lr][lk]     = t0;
        *(uint4*)&As[b][lr][lk + 4] = t1;
        uint4 u0 = make_uint4(f2tf32(w0.x), f2tf32(w0.y), f2tf32(w0.z), f2tf32(w0.w));
        uint4 u1 = make_uint4(f2tf32(w1.x), f2tf32(w1.y), f2tf32(w1.z), f2tf32(w1.w));
        *(uint4*)&Bs[b][bk][bc]     = u0;
        *(uint4*)&Bs[b][bk + 8][bc] = u1;
    };

    {
        float4 a0 = arow_ok ? __ldg((const float4*)(xrow + lk))     : make_float4(0,0,0,0);
        float4 a1 = arow_ok ? __ldg((const float4*)(xrow + lk + 4)) : make_float4(0,0,0,0);
        float4 w0 = __ldg((const float4*)(W + (size_t)bk * D_OUT + bc));
        float4 w1 = __ldg((const float4*)(W + (size_t)(bk + 8) * D_OUT + bc));
        stage(0, a0, a1, w0, w1);
    }
    __syncthreads();

    int buf = 0;
#pragma unroll 1
    for (int k0 = 0; k0 < D_IN; k0 += 16) {
        const int nxt = buf ^ 1;
        const bool has_next = (k0 + 16) < D_IN;
        float4 a0n, a1n, w0n, w1n;
        if (has_next) {
            a0n = arow_ok ? __ldg((const float4*)(xrow + k0 + 16 + lk))     : make_float4(0,0,0,0);
            a1n = arow_ok ? __ldg((const float4*)(xrow + k0 + 16 + lk + 4)) : make_float4(0,0,0,0);
            w0n = __ldg((const float4*)(W + (size_t)(k0 + 16 + bk) * D_OUT + bc));
            w1n = __ldg((const float4*)(W + (size_t)(k0 + 16 + bk + 8) * D_OUT + bc));
        }

#pragma unroll
        for (int ks = 0; ks < 16; ks += 8) {
            uint32_t afr[2][4];
#pragma unroll
            for (int mi = 0; mi < 2; ++mi) {
                const int r0 = warp_m * 32 + mi * 16 + gid;
                afr[mi][0] = As[buf][r0][ks + tig];
                afr[mi][1] = As[buf][r0 + 8][ks + tig];
                afr[mi][2] = As[buf][r0][ks + tig + 4];
                afr[mi][3] = As[buf][r0 + 8][ks + tig + 4];
            }
            uint32_t bfr[8][2];
#pragma unroll
            for (int ni = 0; ni < 8; ++ni) {
                const int c0 = warp_n * 64 + ni * 8 + gid;
                bfr[ni][0] = Bs[buf][ks + tig][c0];
                bfr[ni][1] = Bs[buf][ks + tig + 4][c0];
            }
#pragma unroll
            for (int mi = 0; mi < 2; ++mi)
#pragma unroll
                for (int ni = 0; ni < 8; ++ni)
                    mma_tf32(acc[mi][ni][0], acc[mi][ni][1], acc[mi][ni][2], acc[mi][ni][3],
                             afr[mi][0], afr[mi][1], afr[mi][2], afr[mi][3],
                             bfr[ni][0], bfr[ni][1]);
        }

        if (has_next) {
            stage(nxt, a0n, a1n, w0n, w1n);
            __syncthreads();
        }
        buf = nxt;
    }

#pragma unroll
    for (int mi = 0; mi < 2; ++mi) {
        const int r0 = block_row + warp_m * 32 + mi * 16 + gid;
        const int r1 = r0 + 8;
#pragma unroll
        for (int ni = 0; ni < 8; ++ni) {
            const int c0 = warp_n * 64 + ni * 8 + 2 * tig;
            if (r0 < N_NODES)
                *(__half2*)(g_supph + (size_t)r0 * D_OUT + c0) =
                    __floats2half2_rn(acc[mi][ni][0], acc[mi][ni][1]);
            if (r1 < N_NODES)
                *(__half2*)(g_supph + (size_t)r1 * D_OUT + c0) =
                    __floats2half2_rn(acc[mi][ni][2], acc[mi][ni][3]);
        }
    }
}

// ---------------------------------------------------------------------------
// CSR-by-dst build (g_count arrives zeroed; scan1 re-zeros it after reading)
// ---------------------------------------------------------------------------
__global__ void hist_kernel(const int* __restrict__ edst) {
    int e4 = blockIdx.x * blockDim.x + threadIdx.x;
    if (e4 < N_EDGES / 4) {
        int4 d = ((const int4*)edst)[e4];
        atomicAdd(&g_count[d.x], 1);
        atomicAdd(&g_count[d.y], 1);
        atomicAdd(&g_count[d.z], 1);
        atomicAdd(&g_count[d.w], 1);
    }
}

__global__ __launch_bounds__(SCAN_BLOCK) void scan1_kernel() {
    __shared__ int warp_sums[32];
    const int t = threadIdx.x;
    const int idx = blockIdx.x * SCAN_BLOCK + t;
    const int lane = t & 31;
    const int wrp  = t >> 5;
    int v = (idx < N_NODES) ? g_count[idx] : 0;
    if (idx < N_NODES) g_count[idx] = 0;     // restore invariant for next call
    int incl = v;
#pragma unroll
    for (int off = 1; off < 32; off <<= 1) {
        int n = __shfl_up_sync(0xffffffffu, incl, off);
        if (lane >= off) incl += n;
    }
    if (lane == 31) warp_sums[wrp] = incl;
    __syncthreads();
    if (t < 32) {
        int s = warp_sums[t];
        int si = s;
#pragma unroll
        for (int off = 1; off < 32; off <<= 1) {
            int n = __shfl_up_sync(0xffffffffu, si, off);
            if (t >= off) si += n;
        }
        warp_sums[t] = si - s;   // exclusive warp prefix
    }
    __syncthreads();
    int excl = incl - v + warp_sums[wrp];
    if (idx < N_NODES) g_offsets[idx] = excl;
    if (t == SCAN_BLOCK - 1) g_bsum[blockIdx.x] = excl + v;
}

__global__ void scan2_kernel() {
    __shared__ int ws[4];
    const int t = threadIdx.x;          // 128 threads
    const int lane = t & 31, wrp = t >> 5;
    int v = (t < N_SCAN_BLOCKS) ? g_bsum[t] : 0;
    int incl = v;
#pragma unroll
    for (int off = 1; off < 32; off <<= 1) {
        int n = __shfl_up_sync(0xffffffffu, incl, off);
        if (lane >= off) incl += n;
    }
    if (lane == 31) ws[wrp] = incl;
    __syncthreads();
    int add = 0;
#pragma unroll
    for (int w = 0; w < 4; ++w) add += (w < wrp) ? ws[w] : 0;
    if (t < N_SCAN_BLOCKS) g_bsum[t] = incl - v + add;   // exclusive
}

__global__ void scan3_kernel() {
    int idx = blockIdx.x * blockDim.x + threadIdx.x;
    if (idx < N_NODES) {
        int off = g_offsets[idx] + g_bsum[idx / SCAN_BLOCK];
        g_offsets[idx] = off;
        g_cursor[idx]  = off;
    }
    if (idx == 0) g_offsets[N_NODES] = N_EDGES;
}

__global__ void place_kernel(const int* __restrict__ esrc,
                             const int* __restrict__ edst,
                             const float* __restrict__ ew) {
    int e4 = blockIdx.x * blockDim.x + threadIdx.x;
    if (e4 >= N_EDGES / 4) return;
    int4   s = ((const int4*)esrc)[e4];
    int4   d = ((const int4*)edst)[e4];
    float4 w = ((const float4*)ew)[e4];
    int p0 = atomicAdd(&g_cursor[d.x], 1);
    g_sw[p0] = make_int2(s.x, __float_as_int(w.x));
    int p1 = atomicAdd(&g_cursor[d.y], 1);
    g_sw[p1] = make_int2(s.y, __float_as_int(w.y));
    int p2 = atomicAdd(&g_cursor[d.z], 1);
    g_sw[p2] = make_int2(s.z, __float_as_int(w.z));
    int p3 = atomicAdd(&g_cursor[d.w], 1);
    g_sw[p3] = make_int2(s.w, __float_as_int(w.w));
}

// ---------------------------------------------------------------------------
// Pull: HALF-warp per dst node (16 lanes x 16B = 256B row), 4 edges in flight,
// paired int4 index loads (streaming), streaming out stores.
// fp16 gather (default policy -> support stays L2-resident), fp32 accumulate,
// bias fused. No atomics.
// ---------------------------------------------------------------------------
__global__ __launch_bounds__(256) void pull_kernel(const float* __restrict__ b,
                                                   float* __restrict__ out) {
    const int n   = (blockIdx.x * blockDim.x + threadIdx.x) >> 4;   // halfwarp id
    const int l16 = threadIdx.x & 15;
    if (n >= N_NODES) return;

    int j         = __ldg(&g_offsets[n]);
    const int end = __ldg(&g_offsets[n + 1]);

    float acc[8];
#pragma unroll
    for (int i = 0; i < 8; ++i) acc[i] = 0.0f;

    const uint4* sup = (const uint4*)g_supph;   // 16 uint4 per 256B row

    auto do_edge = [&](int wbits, uint4 u) {
        const float w = __int_as_float(wbits);
#pragma unroll
        for (int h = 0; h < 4; ++h) {
            float2 f = __half22float2(((const __half2*)&u)[h]);
            acc[2*h]   = fmaf(w, f.x, acc[2*h]);
            acc[2*h+1] = fmaf(w, f.y, acc[2*h+1]);
        }
    };

    // peel to even j so int4 loads of g_sw are 16B-aligned
    if ((j & 1) && j < end) {
        int2 sw0 = __ldg(&g_sw[j]);
        uint4 u0 = __ldg(sup + (size_t)sw0.x * 16 + l16);
        do_edge(sw0.y, u0);
        ++j;
    }

    // ---- 4-wide main loop: two streaming int4 index loads + 4 gathers ----
    for (; j + 3 < end; j += 4) {
        int4 p01 = ldg_cs((const int4*)(g_sw + j));       // (src0,w0,src1,w1)
        int4 p23 = ldg_cs((const int4*)(g_sw + j + 2));   // (src2,w2,src3,w3)
        uint4 u0 = __ldg(sup + (size_t)p01.x * 16 + l16);
        uint4 u1 = __ldg(sup + (size_t)p01.z * 16 + l16);
        uint4 u2 = __ldg(sup + (size_t)p23.x * 16 + l16);
        uint4 u3 = __ldg(sup + (size_t)p23.z * 16 + l16);
        do_edge(p01.y, u0);
        do_edge(p01.w, u1);
        do_edge(p23.y, u2);
        do_edge(p23.w, u3);
    }
    // ---- 2-wide tail (j still even) ----
    for (; j + 1 < end; j += 2) {
        int4 p01 = ldg_cs((const int4*)(g_sw + j));
        uint4 u0 = __ldg(sup + (size_t)p01.x * 16 + l16);
        uint4 u1 = __ldg(sup + (size_t)p01.z * 16 + l16);
        do_edge(p01.y, u0);
        do_edge(p01.w, u1);
    }
    // ---- scalar tail ----
    if (j < end) {
        int2 sw0 = __ldg(&g_sw[j]);
        uint4 u0 = __ldg(sup + (size_t)sw0.x * 16 + l16);
        do_edge(sw0.y, u0);
    }

    float4 bv0 = __ldg((const float4*)b + 2 * l16);
    float4 bv1 = __ldg((const float4*)b + 2 * l16 + 1);
    float4 r0 = make_float4(acc[0] + bv0.x, acc[1] + bv0.y, acc[2] + bv0.z, acc[3] + bv0.w);
    float4 r1 = make_float4(acc[4] + bv1.x, acc[5] + bv1.y, acc[6] + bv1.z, acc[7] + bv1.w);
    float4* op = (float4*)out + (size_t)n * (D_OUT / 4) + 2 * l16;
    stg_cs(op, r0);          // evict-first: don't displace support in L2
    stg_cs(op + 1, r1);
}

// ---------------------------------------------------------------------------
// Launch. Inputs: x, edge_src, edge_dst, edge_w, W, b
// GEMM on a forked stream overlaps the CSR build on the main stream.
// Handles are created per call and intentionally leaked (kernel_launch only
// runs for correctness + capture; replays execute the graph).
// ---------------------------------------------------------------------------
extern "C" void kernel_launch(void* const* d_in, const int* in_sizes, int n_in,
                              void* d_out, int out_size) {
    const float* x    = (const float*)d_in[0];
    const int*   esrc = (const int*)d_in[1];
    const int*   edst = (const int*)d_in[2];
    const float* ew   = (const float*)d_in[3];
    const float* W    = (const float*)d_in[4];
    const float* b    = (const float*)d_in[5];
    float* out = (float*)d_out;

    cudaStream_t s1;
    cudaEvent_t ev_fork, ev_join;
    cudaStreamCreateWithFlags(&s1, cudaStreamNonBlocking);
    cudaEventCreateWithFlags(&ev_fork, cudaEventDisableTiming);
    cudaEventCreateWithFlags(&ev_join, cudaEventDisableTiming);

    // fork: GEMM on s1
    cudaEventRecord(ev_fork, 0);
    cudaStreamWaitEvent(s1, ev_fork, 0);
    gemm_tf32_kernel<<<(N_NODES + 127) / 128, 256, 0, s1>>>(x, W);
    cudaEventRecord(ev_join, s1);

    // CSR build on main stream (independent of GEMM)
    hist_kernel<<<(N_EDGES / 4 + 255) / 256, 256>>>(edst);
    scan1_kernel<<<N_SCAN_BLOCKS, SCAN_BLOCK>>>();
    scan2_kernel<<<1, 128>>>();
    scan3_kernel<<<(N_NODES + 255) / 256, 256>>>();
    place_kernel<<<(N_EDGES / 4 + 255) / 256, 256>>>(esrc, edst, ew);

    // join: pull needs both g_supph (s1) and CSR (main)
    cudaStreamWaitEvent(0, ev_join, 0);
    long long pull_threads = (long long)N_NODES * 16;
    pull_kernel<<<(int)((pull_threads + 255) / 256), 256>>>(b, out);
}

// round 14
// speedup vs baseline: 1.4385x; 1.4385x over previous
#include <cuda_runtime.h>
#include <cuda_bf16.h>
#include <cuda_fp16.h>
#include <cstdint>

#define N_NODES 100000
#define N_EDGES 1600000
#define D_IN    256
#define D_OUT   128

#define SCAN_BLOCK 1024
#define N_SCAN_BLOCKS ((N_NODES + SCAN_BLOCK - 1) / SCAN_BLOCK)   // 98

typedef unsigned long long ull;

// Device scratch (static __device__ arrays only; no allocation anywhere).
// g_count is loader-zero-initialized and re-zeroed by scan1 on every call,
// so hist always sees zeros (invariant maintained across calls/replays).
__device__ __half g_supph[(size_t)N_NODES * D_OUT];    // 25.6 MB fp16 support
__device__ int   g_count[N_NODES];
__device__ int   g_offsets[N_NODES + 1];
__device__ int   g_cursor[N_NODES];
__device__ int   g_bsum[N_SCAN_BLOCKS];
__device__ __align__(16) int2 g_sw[N_EDGES];           // packed (src, bits(w)), 16B-aligned

// ---------------------------------------------------------------------------
// helpers
// ---------------------------------------------------------------------------
__device__ __forceinline__ uint32_t f2tf32(float f) {
    uint32_t r;
    asm("cvt.rna.tf32.f32 %0, %1;" : "=r"(r) : "f"(f));
    return r;
}

__device__ __forceinline__ void mma_tf32(float& d0, float& d1, float& d2, float& d3,
                                         uint32_t a0, uint32_t a1, uint32_t a2, uint32_t a3,
                                         uint32_t b0, uint32_t b1) {
    asm volatile(
        "mma.sync.aligned.m16n8k8.row.col.f32.tf32.tf32.f32 "
        "{%0,%1,%2,%3}, {%4,%5,%6,%7}, {%8,%9}, {%0,%1,%2,%3};"
        : "+f"(d0), "+f"(d1), "+f"(d2), "+f"(d3)
        : "r"(a0), "r"(a1), "r"(a2), "r"(a3), "r"(b0), "r"(b1));
}

// ---------------------------------------------------------------------------
// GEMM: support = x @ W via tf32 mma. BM=128, BN=128, BK=16.
// 256 threads = 8 warps in 4(M) x 2(N): 32x64 per warp, 32 mmas per barrier.
// A stride 20 / B stride 136: fragment LDS conflict-free.
// ---------------------------------------------------------------------------
__global__ __launch_bounds__(256) void gemm_tf32_kernel(const float* __restrict__ x,
                                                        const float* __restrict__ W) {
    __shared__ uint32_t As[2][128][20];
    __shared__ uint32_t Bs[2][16][136];

    const int tid  = threadIdx.x;
    const int wid  = tid >> 5;
    const int lane = tid & 31;
    const int gid  = lane >> 2;
    const int tig  = lane & 3;
    const int warp_m = wid & 3;
    const int warp_n = wid >> 2;
    const int block_row = blockIdx.x * 128;

    const int lr = tid >> 1;
    const int lk = (tid & 1) * 8;
    const int bk = tid >> 5;
    const int bc = (tid & 31) * 4;

    const int grow = block_row + lr;
    const bool arow_ok = (grow < N_NODES);
    const float* xrow = x + (size_t)grow * D_IN;

    float acc[2][8][4];
#pragma unroll
    for (int mi = 0; mi < 2; ++mi)
#pragma unroll
        for (int ni = 0; ni < 8; ++ni)
#pragma unroll
            for (int c = 0; c < 4; ++c) acc[mi][ni][c] = 0.0f;

    auto stage = [&](int b, float4 a0, float4 a1, float4 w0, float4 w1) {
        uint4 t0 = make_uint4(f2tf32(a0.x), f2tf32(a0.y), f2tf32(a0.z), f2tf32(a0.w));
        uint4 t1 = make_uint4(f2tf32(a1.x), f2tf32(a1.y), f2tf32(a1.z), f2tf32(a1.w));
        *(uint4*)&As[b][lr][lk]     = t0;
        *(uint4*)&As[b][lr][lk + 4] = t1;
        uint4 u0 = make_uint4(f2tf32(w0.x), f2tf32(w0.y), f2tf32(w0.z), f2tf32(w0.w));
        uint4 u1 = make_uint4(f2tf32(w1.x), f2tf32(w1.y), f2tf32(w1.z), f2tf32(w1.w));
        *(uint4*)&Bs[b][bk][bc]     = u0;
        *(uint4*)&Bs[b][bk + 8][bc] = u1;
    };

    {
        float4 a0 = arow_ok ? __ldg((const float4*)(xrow + lk))     : make_float4(0,0,0,0);
        float4 a1 = arow_ok ? __ldg((const float4*)(xrow + lk + 4)) : make_float4(0,0,0,0);
        float4 w0 = __ldg((const float4*)(W + (size_t)bk * D_OUT + bc));
        float4 w1 = __ldg((const float4*)(W + (size_t)(bk + 8) * D_OUT + bc));
        stage(0, a0, a1, w0, w1);
    }
    __syncthreads();

    int buf = 0;
#pragma unroll 1
    for (int k0 = 0; k0 < D_IN; k0 += 16) {
        const int nxt = buf ^ 1;
        const bool has_next = (k0 + 16) < D_IN;
        float4 a0n, a1n, w0n, w1n;
        if (has_next) {
            a0n = arow_ok ? __ldg((const float4*)(xrow + k0 + 16 + lk))     : make_float4(0,0,0,0);
            a1n = arow_ok ? __ldg((const float4*)(xrow + k0 + 16 + lk + 4)) : make_float4(0,0,0,0);
            w0n = __ldg((const float4*)(W + (size_t)(k0 + 16 + bk) * D_OUT + bc));
            w1n = __ldg((const float4*)(W + (size_t)(k0 + 16 + bk + 8) * D_OUT + bc));
        }

#pragma unroll
        for (int ks = 0; ks < 16; ks += 8) {
            uint32_t afr[2][4];
#pragma unroll
            for (int mi = 0; mi < 2; ++mi) {
                const int r0 = warp_m * 32 + mi * 16 + gid;
                afr[mi][0] = As[buf][r0][ks + tig];
                afr[mi][1] = As[buf][r0 + 8][ks + tig];
                afr[mi][2] = As[buf][r0][ks + tig + 4];
                afr[mi][3] = As[buf][r0 + 8][ks + tig + 4];
            }
            uint32_t bfr[8][2];
#pragma unroll
            for (int ni = 0; ni < 8; ++ni) {
                const int c0 = warp_n * 64 + ni * 8 + gid;
                bfr[ni][0] = Bs[buf][ks + tig][c0];
                bfr[ni][1] = Bs[buf][ks + tig + 4][c0];
            }
#pragma unroll
            for (int mi = 0; mi < 2; ++mi)
#pragma unroll
                for (int ni = 0; ni < 8; ++ni)
                    mma_tf32(acc[mi][ni][0], acc[mi][ni][1], acc[mi][ni][2], acc[mi][ni][3],
                             afr[mi][0], afr[mi][1], afr[mi][2], afr[mi][3],
                             bfr[ni][0], bfr[ni][1]);
        }

        if (has_next) {
            stage(nxt, a0n, a1n, w0n, w1n);
            __syncthreads();
        }
        buf = nxt;
    }

#pragma unroll
    for (int mi = 0; mi < 2; ++mi) {
        const int r0 = block_row + warp_m * 32 + mi * 16 + gid;
        const int r1 = r0 + 8;
#pragma unroll
        for (int ni = 0; ni < 8; ++ni) {
            const int c0 = warp_n * 64 + ni * 8 + 2 * tig;
            if (r0 < N_NODES)
                *(__half2*)(g_supph + (size_t)r0 * D_OUT + c0) =
                    __floats2half2_rn(acc[mi][ni][0], acc[mi][ni][1]);
            if (r1 < N_NODES)
                *(__half2*)(g_supph + (size_t)r1 * D_OUT + c0) =
                    __floats2half2_rn(acc[mi][ni][2], acc[mi][ni][3]);
        }
    }
}

// ---------------------------------------------------------------------------
// CSR-by-dst build (g_count arrives zeroed; scan1 re-zeros it after reading)
// ---------------------------------------------------------------------------
__global__ void hist_kernel(const int* __restrict__ edst) {
    int e4 = blockIdx.x * blockDim.x + threadIdx.x;
    if (e4 < N_EDGES / 4) {
        int4 d = ((const int4*)edst)[e4];
        atomicAdd(&g_count[d.x], 1);
        atomicAdd(&g_count[d.y], 1);
        atomicAdd(&g_count[d.z], 1);
        atomicAdd(&g_count[d.w], 1);
    }
}

__global__ __launch_bounds__(SCAN_BLOCK) void scan1_kernel() {
    __shared__ int warp_sums[32];
    const int t = threadIdx.x;
    const int idx = blockIdx.x * SCAN_BLOCK + t;
    const int lane = t & 31;
    const int wrp  = t >> 5;
    int v = (idx < N_NODES) ? g_count[idx] : 0;
    if (idx < N_NODES) g_count[idx] = 0;     // restore invariant for next call
    int incl = v;
#pragma unroll
    for (int off = 1; off < 32; off <<= 1) {
        int n = __shfl_up_sync(0xffffffffu, incl, off);
        if (lane >= off) incl += n;
    }
    if (lane == 31) warp_sums[wrp] = incl;
    __syncthreads();
    if (t < 32) {
        int s = warp_sums[t];
        int si = s;
#pragma unroll
        for (int off = 1; off < 32; off <<= 1) {
            int n = __shfl_up_sync(0xffffffffu, si, off);
            if (t >= off) si += n;
        }
        warp_sums[t] = si - s;   // exclusive warp prefix
    }
    __syncthreads();
    int excl = incl - v + warp_sums[wrp];
    if (idx < N_NODES) g_offsets[idx] = excl;
    if (t == SCAN_BLOCK - 1) g_bsum[blockIdx.x] = excl + v;
}

__global__ void scan2_kernel() {
    __shared__ int ws[4];
    const int t = threadIdx.x;          // 128 threads
    const int lane = t & 31, wrp = t >> 5;
    int v = (t < N_SCAN_BLOCKS) ? g_bsum[t] : 0;
    int incl = v;
#pragma unroll
    for (int off = 1; off < 32; off <<= 1) {
        int n = __shfl_up_sync(0xffffffffu, incl, off);
        if (lane >= off) incl += n;
    }
    if (lane == 31) ws[wrp] = incl;
    __syncthreads();
    int add = 0;
#pragma unroll
    for (int w = 0; w < 4; ++w) add += (w < wrp) ? ws[w] : 0;
    if (t < N_SCAN_BLOCKS) g_bsum[t] = incl - v + add;   // exclusive
}

__global__ void scan3_kernel() {
    int idx = blockIdx.x * blockDim.x + threadIdx.x;
    if (idx < N_NODES) {
        int off = g_offsets[idx] + g_bsum[idx / SCAN_BLOCK];
        g_offsets[idx] = off;
        g_cursor[idx]  = off;
    }
    if (idx == 0) g_offsets[N_NODES] = N_EDGES;
}

__global__ void place_kernel(const int* __restrict__ esrc,
                             const int* __restrict__ edst,
                             const float* __restrict__ ew) {
    int e4 = blockIdx.x * blockDim.x + threadIdx.x;
    if (e4 >= N_EDGES / 4) return;
    int4   s = ((const int4*)esrc)[e4];
    int4   d = ((const int4*)edst)[e4];
    float4 w = ((const float4*)ew)[e4];
    int p0 = atomicAdd(&g_cursor[d.x], 1);
    g_sw[p0] = make_int2(s.x, __float_as_int(w.x));
    int p1 = atomicAdd(&g_cursor[d.y], 1);
    g_sw[p1] = make_int2(s.y, __float_as_int(w.y));
    int p2 = atomicAdd(&g_cursor[d.z], 1);
    g_sw[p2] = make_int2(s.z, __float_as_int(w.z));
    int p3 = atomicAdd(&g_cursor[d.w], 1);
    g_sw[p3] = make_int2(s.w, __float_as_int(w.w));
}

// ---------------------------------------------------------------------------
// Pull: HALF-warp per dst node (16 lanes x 16B = 256B row), 4 edges in flight,
// paired int4 index loads (broadcast, default cache policy). fp16 gather,
// fp32 accumulate, bias fused. No atomics, no cache hints.
// ---------------------------------------------------------------------------
__global__ __launch_bounds__(256) void pull_kernel(const float* __restrict__ b,
                                                   float* __restrict__ out) {
    const int n   = (blockIdx.x * blockDim.x + threadIdx.x) >> 4;   // halfwarp id
    const int l16 = threadIdx.x & 15;
    if (n >= N_NODES) return;

    int j         = __ldg(&g_offsets[n]);
    const int end = __ldg(&g_offsets[n + 1]);

    float acc[8];
#pragma unroll
    for (int i = 0; i < 8; ++i) acc[i] = 0.0f;

    const uint4* sup = (const uint4*)g_supph;   // 16 uint4 per 256B row

    auto do_edge = [&](int wbits, uint4 u) {
        const float w = __int_as_float(wbits);
#pragma unroll
        for (int h = 0; h < 4; ++h) {
            float2 f = __half22float2(((const __half2*)&u)[h]);
            acc[2*h]   = fmaf(w, f.x, acc[2*h]);
            acc[2*h+1] = fmaf(w, f.y, acc[2*h+1]);
        }
    };

    // peel to even j so int4 loads of g_sw are 16B-aligned
    if ((j & 1) && j < end) {
        int2 sw0 = __ldg(&g_sw[j]);
        uint4 u0 = __ldg(sup + (size_t)sw0.x * 16 + l16);
        do_edge(sw0.y, u0);
        ++j;
    }

    // ---- 4-wide main loop: two int4 index loads + 4 gathers in flight ----
    for (; j + 3 < end; j += 4) {
        int4 p01 = __ldg((const int4*)(g_sw + j));       // (src0,w0,src1,w1)
        int4 p23 = __ldg((const int4*)(g_sw + j + 2));   // (src2,w2,src3,w3)
        uint4 u0 = __ldg(sup + (size_t)p01.x * 16 + l16);
        uint4 u1 = __ldg(sup + (size_t)p01.z * 16 + l16);
        uint4 u2 = __ldg(sup + (size_t)p23.x * 16 + l16);
        uint4 u3 = __ldg(sup + (size_t)p23.z * 16 + l16);
        do_edge(p01.y, u0);
        do_edge(p01.w, u1);
        do_edge(p23.y, u2);
        do_edge(p23.w, u3);
    }
    // ---- 2-wide tail (j still even) ----
    for (; j + 1 < end; j += 2) {
        int4 p01 = __ldg((const int4*)(g_sw + j));
        uint4 u0 = __ldg(sup + (size_t)p01.x * 16 + l16);
        uint4 u1 = __ldg(sup + (size_t)p01.z * 16 + l16);
        do_edge(p01.y, u0);
        do_edge(p01.w, u1);
    }
    // ---- scalar tail ----
    if (j < end) {
        int2 sw0 = __ldg(&g_sw[j]);
        uint4 u0 = __ldg(sup + (size_t)sw0.x * 16 + l16);
        do_edge(sw0.y, u0);
    }

    float4 bv0 = __ldg((const float4*)b + 2 * l16);
    float4 bv1 = __ldg((const float4*)b + 2 * l16 + 1);
    float4 r0 = make_float4(acc[0] + bv0.x, acc[1] + bv0.y, acc[2] + bv0.z, acc[3] + bv0.w);
    float4 r1 = make_float4(acc[4] + bv1.x, acc[5] + bv1.y, acc[6] + bv1.z, acc[7] + bv1.w);
    float4* op = (float4*)out + (size_t)n * (D_OUT / 4) + 2 * l16;
    op[0] = r0;
    op[1] = r1;
}

// ---------------------------------------------------------------------------
// Launch. Inputs: x, edge_src, edge_dst, edge_w, W, b
// GEMM on a forked stream overlaps the CSR build on the main stream.
// Handles are created per call and intentionally leaked (kernel_launch only
// runs for correctness + capture; replays execute the graph).
// ---------------------------------------------------------------------------
extern "C" void kernel_launch(void* const* d_in, const int* in_sizes, int n_in,
                              void* d_out, int out_size) {
    const float* x    = (const float*)d_in[0];
    const int*   esrc = (const int*)d_in[1];
    const int*   edst = (const int*)d_in[2];
    const float* ew   = (const float*)d_in[3];
    const float* W    = (const float*)d_in[4];
    const float* b    = (const float*)d_in[5];
    float* out = (float*)d_out;

    cudaStream_t s1;
    cudaEvent_t ev_fork, ev_join;
    cudaStreamCreateWithFlags(&s1, cudaStreamNonBlocking);
    cudaEventCreateWithFlags(&ev_fork, cudaEventDisableTiming);
    cudaEventCreateWithFlags(&ev_join, cudaEventDisableTiming);

    // fork: GEMM on s1
    cudaEventRecord(ev_fork, 0);
    cudaStreamWaitEvent(s1, ev_fork, 0);
    gemm_tf32_kernel<<<(N_NODES + 127) / 128, 256, 0, s1>>>(x, W);
    cudaEventRecord(ev_join, s1);

    // CSR build on main stream (independent of GEMM)
    hist_kernel<<<(N_EDGES / 4 + 255) / 256, 256>>>(edst);
    scan1_kernel<<<N_SCAN_BLOCKS, SCAN_BLOCK>>>();
    scan2_kernel<<<1, 128>>>();
    scan3_kernel<<<(N_NODES + 255) / 256, 256>>>();
    place_kernel<<<(N_EDGES / 4 + 255) / 256, 256>>>(esrc, edst, ew);

    // join: pull needs both g_supph (s1) and CSR (main)
    cudaStreamWaitEvent(0, ev_join, 0);
    long long pull_threads = (long long)N_NODES * 16;
    pull_kernel<<<(int)((pull_threads + 255) / 256), 256>>>(b, out);
}

// round 15
// speedup vs baseline: 1.5099x; 1.0496x over previous
#include <cuda_runtime.h>
#include <cuda_bf16.h>
#include <cuda_fp16.h>
#include <cstdint>

#define N_NODES 100000
#define N_EDGES 1600000
#define D_IN    256
#define D_OUT   128

#define SCAN_BLOCK 1024
#define N_SCAN_BLOCKS ((N_NODES + SCAN_BLOCK - 1) / SCAN_BLOCK)   // 98

typedef unsigned long long ull;

// Device scratch (static __device__ arrays only; no allocation anywhere).
// g_count is loader-zero-initialized and re-zeroed by the scan on every call.
// g_scanstate is re-zeroed by hist_kernel (stream-ordered before the scan).
__device__ __half g_supph[(size_t)N_NODES * D_OUT];    // 25.6 MB fp16 support
__device__ int   g_count[N_NODES];
__device__ int   g_offsets[N_NODES + 1];
__device__ int   g_cursor[N_NODES];
__device__ volatile ull g_scanstate[N_SCAN_BLOCKS];    // packed (flag<<32 | sum)
__device__ __align__(16) int2 g_sw[N_EDGES];           // packed (src, bits(w))

// ---------------------------------------------------------------------------
// helpers
// ---------------------------------------------------------------------------
__device__ __forceinline__ uint32_t f2tf32(float f) {
    uint32_t r;
    asm("cvt.rna.tf32.f32 %0, %1;" : "=r"(r) : "f"(f));
    return r;
}

__device__ __forceinline__ void mma_tf32(float& d0, float& d1, float& d2, float& d3,
                                         uint32_t a0, uint32_t a1, uint32_t a2, uint32_t a3,
                                         uint32_t b0, uint32_t b1) {
    asm volatile(
        "mma.sync.aligned.m16n8k8.row.col.f32.tf32.tf32.f32 "
        "{%0,%1,%2,%3}, {%4,%5,%6,%7}, {%8,%9}, {%0,%1,%2,%3};"
        : "+f"(d0), "+f"(d1), "+f"(d2), "+f"(d3)
        : "r"(a0), "r"(a1), "r"(a2), "r"(a3), "r"(b0), "r"(b1));
}

// ---------------------------------------------------------------------------
// GEMM: support = x @ W via tf32 mma. BM=128, BN=128, BK=16.
// 256 threads = 8 warps in 4(M) x 2(N): 32x64 per warp, 32 mmas per barrier.
// A stride 20 / B stride 136: fragment LDS conflict-free.
// ---------------------------------------------------------------------------
__global__ __launch_bounds__(256) void gemm_tf32_kernel(const float* __restrict__ x,
                                                        const float* __restrict__ W) {
    __shared__ uint32_t As[2][128][20];
    __shared__ uint32_t Bs[2][16][136];

    const int tid  = threadIdx.x;
    const int wid  = tid >> 5;
    const int lane = tid & 31;
    const int gid  = lane >> 2;
    const int tig  = lane & 3;
    const int warp_m = wid & 3;
    const int warp_n = wid >> 2;
    const int block_row = blockIdx.x * 128;

    const int lr = tid >> 1;
    const int lk = (tid & 1) * 8;
    const int bk = tid >> 5;
    const int bc = (tid & 31) * 4;

    const int grow = block_row + lr;
    const bool arow_ok = (grow < N_NODES);
    const float* xrow = x + (size_t)grow * D_IN;

    float acc[2][8][4];
#pragma unroll
    for (int mi = 0; mi < 2; ++mi)
#pragma unroll
        for (int ni = 0; ni < 8; ++ni)
#pragma unroll
            for (int c = 0; c < 4; ++c) acc[mi][ni][c] = 0.0f;

    auto stage = [&](int b, float4 a0, float4 a1, float4 w0, float4 w1) {
        uint4 t0 = make_uint4(f2tf32(a0.x), f2tf32(a0.y), f2tf32(a0.z), f2tf32(a0.w));
        uint4 t1 = make_uint4(f2tf32(a1.x), f2tf32(a1.y), f2tf32(a1.z), f2tf32(a1.w));
        *(uint4*)&As[b][lr][lk]     = t0;
        *(uint4*)&As[b][lr][lk + 4] = t1;
        uint4 u0 = make_uint4(f2tf32(w0.x), f2tf32(w0.y), f2tf32(w0.z), f2tf32(w0.w));
        uint4 u1 = make_uint4(f2tf32(w1.x), f2tf32(w1.y), f2tf32(w1.z), f2tf32(w1.w));
        *(uint4*)&Bs[b][bk][bc]     = u0;
        *(uint4*)&Bs[b][bk + 8][bc] = u1;
    };

    {
        float4 a0 = arow_ok ? __ldg((const float4*)(xrow + lk))     : make_float4(0,0,0,0);
        float4 a1 = arow_ok ? __ldg((const float4*)(xrow + lk + 4)) : make_float4(0,0,0,0);
        float4 w0 = __ldg((const float4*)(W + (size_t)bk * D_OUT + bc));
        float4 w1 = __ldg((const float4*)(W + (size_t)(bk + 8) * D_OUT + bc));
        stage(0, a0, a1, w0, w1);
    }
    __syncthreads();

    int buf = 0;
#pragma unroll 1
    for (int k0 = 0; k0 < D_IN; k0 += 16) {
        const int nxt = buf ^ 1;
        const bool has_next = (k0 + 16) < D_IN;
        float4 a0n, a1n, w0n, w1n;
        if (has_next) {
            a0n = arow_ok ? __ldg((const float4*)(xrow + k0 + 16 + lk))     : make_float4(0,0,0,0);
            a1n = arow_ok ? __ldg((const float4*)(xrow + k0 + 16 + lk + 4)) : make_float4(0,0,0,0);
            w0n = __ldg((const float4*)(W + (size_t)(k0 + 16 + bk) * D_OUT + bc));
            w1n = __ldg((const float4*)(W + (size_t)(k0 + 16 + bk + 8) * D_OUT + bc));
        }

#pragma unroll
        for (int ks = 0; ks < 16; ks += 8) {
            uint32_t afr[2][4];
#pragma unroll
            for (int mi = 0; mi < 2; ++mi) {
                const int r0 = warp_m * 32 + mi * 16 + gid;
                afr[mi][0] = As[buf][r0][ks + tig];
                afr[mi][1] = As[buf][r0 + 8][ks + tig];
                afr[mi][2] = As[buf][r0][ks + tig + 4];
                afr[mi][3] = As[buf][r0 + 8][ks + tig + 4];
            }
            uint32_t bfr[8][2];
#pragma unroll
            for (int ni = 0; ni < 8; ++ni) {
                const int c0 = warp_n * 64 + ni * 8 + gid;
                bfr[ni][0] = Bs[buf][ks + tig][c0];
                bfr[ni][1] = Bs[buf][ks + tig + 4][c0];
            }
#pragma unroll
            for (int mi = 0; mi < 2; ++mi)
#pragma unroll
                for (int ni = 0; ni < 8; ++ni)
                    mma_tf32(acc[mi][ni][0], acc[mi][ni][1], acc[mi][ni][2], acc[mi][ni][3],
                             afr[mi][0], afr[mi][1], afr[mi][2], afr[mi][3],
                             bfr[ni][0], bfr[ni][1]);
        }

        if (has_next) {
            stage(nxt, a0n, a1n, w0n, w1n);
            __syncthreads();
        }
        buf = nxt;
    }

#pragma unroll
    for (int mi = 0; mi < 2; ++mi) {
        const int r0 = block_row + warp_m * 32 + mi * 16 + gid;
        const int r1 = r0 + 8;
#pragma unroll
        for (int ni = 0; ni < 8; ++ni) {
            const int c0 = warp_n * 64 + ni * 8 + 2 * tig;
            if (r0 < N_NODES)
                *(__half2*)(g_supph + (size_t)r0 * D_OUT + c0) =
                    __floats2half2_rn(acc[mi][ni][0], acc[mi][ni][1]);
            if (r1 < N_NODES)
                *(__half2*)(g_supph + (size_t)r1 * D_OUT + c0) =
                    __floats2half2_rn(acc[mi][ni][2], acc[mi][ni][3]);
        }
    }
}

// ---------------------------------------------------------------------------
// hist: edge-dst histogram. Also re-zeros the scan lookback state (stream-
// ordered before the scan kernel; 1563 blocks >= 98 flags).
// ---------------------------------------------------------------------------
__global__ void hist_kernel(const int* __restrict__ edst) {
    if (threadIdx.x == 0 && blockIdx.x < N_SCAN_BLOCKS)
        g_scanstate[blockIdx.x] = 0ull;
    int e4 = blockIdx.x * blockDim.x + threadIdx.x;
    if (e4 < N_EDGES / 4) {
        int4 d = ((const int4*)edst)[e4];
        atomicAdd(&g_count[d.x], 1);
        atomicAdd(&g_count[d.y], 1);
        atomicAdd(&g_count[d.z], 1);
        atomicAdd(&g_count[d.w], 1);
    }
}

// ---------------------------------------------------------------------------
// Single-pass decoupled-lookback scan: replaces scan1+scan2+scan3.
// 98 blocks (all co-resident on 148 SMs -> no deadlock). Each block scans its
// 1024 counts, publishes (flag,sum) packed in 8B, lookback-accumulates its
// exclusive base, writes offsets+cursor, and re-zeros g_count.
// flag: 1 = block aggregate, 2 = inclusive prefix.
// ---------------------------------------------------------------------------
__global__ __launch_bounds__(SCAN_BLOCK) void scan_fused_kernel() {
    __shared__ int warp_sums[32];
    __shared__ int s_total;
    __shared__ int s_base;
    const int t = threadIdx.x;
    const int bid = blockIdx.x;
    const int idx = bid * SCAN_BLOCK + t;
    const int lane = t & 31;
    const int wrp  = t >> 5;

    int v = (idx < N_NODES) ? g_count[idx] : 0;
    if (idx < N_NODES) g_count[idx] = 0;     // restore invariant for next call

    int incl = v;
#pragma unroll
    for (int off = 1; off < 32; off <<= 1) {
        int n = __shfl_up_sync(0xffffffffu, incl, off);
        if (lane >= off) incl += n;
    }
    if (lane == 31) warp_sums[wrp] = incl;
    __syncthreads();
    if (t < 32) {
        int s = warp_sums[t];
        int si = s;
#pragma unroll
        for (int off = 1; off < 32; off <<= 1) {
            int n = __shfl_up_sync(0xffffffffu, si, off);
            if (t >= off) si += n;
        }
        warp_sums[t] = si - s;   // exclusive warp prefix
    }
    __syncthreads();
    const int excl = incl - v + warp_sums[wrp];
    if (t == SCAN_BLOCK - 1) s_total = excl + v;
    __syncthreads();
    const int block_total = s_total;

    // publish + windowed lookback (warp 0)
    if (t < 32) {
        if (bid == 0) {
            if (t == 0) {
                atomicExch((ull*)&g_scanstate[0], (2ull << 32) | (uint32_t)block_total);
                s_base = 0;
            }
        } else {
            if (t == 0)
                atomicExch((ull*)&g_scanstate[bid], (1ull << 32) | (uint32_t)block_total);
            int running = 0;
            int p = bid - 1;
            while (true) {
                const int i = p - lane;              // lane 0 = nearest predecessor
                ull st;
                do {
                    st = (i >= 0) ? g_scanstate[i] : (2ull << 32);
                } while ((uint32_t)(st >> 32) == 0u);
                const uint32_t flag = (uint32_t)(st >> 32);
                const int val = (int)(uint32_t)st;
                const unsigned m2 = __ballot_sync(0xffffffffu, flag == 2u);
                if (m2) {
                    const int l2 = __ffs(m2) - 1;    // nearest prefix-complete block
                    int contrib = (lane <= l2) ? val : 0;
#pragma unroll
                    for (int off = 16; off; off >>= 1)
                        contrib += __shfl_down_sync(0xffffffffu, contrib, off);
                    running += __shfl_sync(0xffffffffu, contrib, 0);
                    break;
                } else {
                    int contrib = (i >= 0) ? val : 0;
#pragma unroll
                    for (int off = 16; off; off >>= 1)
                        contrib += __shfl_down_sync(0xffffffffu, contrib, off);
                    running += __shfl_sync(0xffffffffu, contrib, 0);
                    p -= 32;
                }
            }
            if (t == 0) {
                atomicExch((ull*)&g_scanstate[bid],
                           (2ull << 32) | (uint32_t)(running + block_total));
                s_base = running;
            }
        }
    }
    __syncthreads();

    if (idx < N_NODES) {
        const int off = s_base + excl;
        g_offsets[idx] = off;
        g_cursor[idx]  = off;
    }
    if (idx == 0) g_offsets[N_NODES] = N_EDGES;
}

// ---------------------------------------------------------------------------
// place: bucket edges by dst (atomic cursor), 4 edges per thread vectorized.
// ---------------------------------------------------------------------------
__global__ void place_kernel(const int* __restrict__ esrc,
                             const int* __restrict__ edst,
                             const float* __restrict__ ew) {
    int e4 = blockIdx.x * blockDim.x + threadIdx.x;
    if (e4 >= N_EDGES / 4) return;
    int4   s = ((const int4*)esrc)[e4];
    int4   d = ((const int4*)edst)[e4];
    float4 w = ((const float4*)ew)[e4];
    int p0 = atomicAdd(&g_cursor[d.x], 1);
    g_sw[p0] = make_int2(s.x, __float_as_int(w.x));
    int p1 = atomicAdd(&g_cursor[d.y], 1);
    g_sw[p1] = make_int2(s.y, __float_as_int(w.y));
    int p2 = atomicAdd(&g_cursor[d.z], 1);
    g_sw[p2] = make_int2(s.z, __float_as_int(w.z));
    int p3 = atomicAdd(&g_cursor[d.w], 1);
    g_sw[p3] = make_int2(s.w, __float_as_int(w.w));
}

// ---------------------------------------------------------------------------
// Pull: HALF-warp per dst node (16 lanes x 16B = 256B row), 4 edges in flight.
// fp16 gather, fp32 accumulate, bias fused. No atomics. (Exact R8 shape —
// the measured local optimum.)
// ---------------------------------------------------------------------------
__global__ __launch_bounds__(256) void pull_kernel(const float* __restrict__ b,
                                                   float* __restrict__ out) {
    const int n   = (blockIdx.x * blockDim.x + threadIdx.x) >> 4;   // halfwarp id
    const int l16 = threadIdx.x & 15;
    if (n >= N_NODES) return;

    const int start = __ldg(&g_offsets[n]);
    const int end   = __ldg(&g_offsets[n + 1]);

    float acc[8];
#pragma unroll
    for (int i = 0; i < 8; ++i) acc[i] = 0.0f;

    const uint4* sup = (const uint4*)g_supph;   // 16 uint4 per 256B row

    int j = start;
    for (; j + 3 < end; j += 4) {
        int2 sw0 = __ldg(&g_sw[j]);
        int2 sw1 = __ldg(&g_sw[j + 1]);
        int2 sw2 = __ldg(&g_sw[j + 2]);
        int2 sw3 = __ldg(&g_sw[j + 3]);
        uint4 u0 = __ldg(sup + (size_t)sw0.x * 16 + l16);
        uint4 u1 = __ldg(sup + (size_t)sw1.x * 16 + l16);
        uint4 u2 = __ldg(sup + (size_t)sw2.x * 16 + l16);
        uint4 u3 = __ldg(sup + (size_t)sw3.x * 16 + l16);
        float w0 = __int_as_float(sw0.y), w1 = __int_as_float(sw1.y);
        float w2 = __int_as_float(sw2.y), w3 = __int_as_float(sw3.y);

#pragma unroll
        for (int h = 0; h < 4; ++h) {
            float2 f0 = __half22float2(((const __half2*)&u0)[h]);
            float2 f1 = __half22float2(((const __half2*)&u1)[h]);
            float2 f2 = __half22float2(((const __half2*)&u2)[h]);
            float2 f3 = __half22float2(((const __half2*)&u3)[h]);
            acc[2*h]   = fmaf(w0, f0.x, acc[2*h]);
            acc[2*h+1] = fmaf(w0, f0.y, acc[2*h+1]);
            acc[2*h]   = fmaf(w1, f1.x, acc[2*h]);
            acc[2*h+1] = fmaf(w1, f1.y, acc[2*h+1]);
            acc[2*h]   = fmaf(w2, f2.x, acc[2*h]);
            acc[2*h+1] = fmaf(w2, f2.y, acc[2*h+1]);
            acc[2*h]   = fmaf(w3, f3.x, acc[2*h]);
            acc[2*h+1] = fmaf(w3, f3.y, acc[2*h+1]);
        }
    }
    for (; j < end; ++j) {
        int2 sw0 = __ldg(&g_sw[j]);
        float w0 = __int_as_float(sw0.y);
        uint4 u0 = __ldg(sup + (size_t)sw0.x * 16 + l16);
#pragma unroll
        for (int h = 0; h < 4; ++h) {
            float2 f0 = __half22float2(((const __half2*)&u0)[h]);
            acc[2*h]   = fmaf(w0, f0.x, acc[2*h]);
            acc[2*h+1] = fmaf(w0, f0.y, acc[2*h+1]);
        }
    }

    float4 bv0 = __ldg((const float4*)b + 2 * l16);
    float4 bv1 = __ldg((const float4*)b + 2 * l16 + 1);
    float4 r0 = make_float4(acc[0] + bv0.x, acc[1] + bv0.y, acc[2] + bv0.z, acc[3] + bv0.w);
    float4 r1 = make_float4(acc[4] + bv1.x, acc[5] + bv1.y, acc[6] + bv1.z, acc[7] + bv1.w);
    float4* op = (float4*)out + (size_t)n * (D_OUT / 4) + 2 * l16;
    op[0] = r0;
    op[1] = r1;
}

// ---------------------------------------------------------------------------
// Launch. Inputs: x, edge_src, edge_dst, edge_w, W, b
// GEMM on a forked stream overlaps the CSR build on the main stream.
// Handles are created per call and intentionally leaked (kernel_launch only
// runs for correctness + capture; replays execute the graph).
// ---------------------------------------------------------------------------
extern "C" void kernel_launch(void* const* d_in, const int* in_sizes, int n_in,
                              void* d_out, int out_size) {
    const float* x    = (const float*)d_in[0];
    const int*   esrc = (const int*)d_in[1];
    const int*   edst = (const int*)d_in[2];
    const float* ew   = (const float*)d_in[3];
    const float* W    = (const float*)d_in[4];
    const float* b    = (const float*)d_in[5];
    float* out = (float*)d_out;

    cudaStream_t s1;
    cudaEvent_t ev_fork, ev_join;
    cudaStreamCreateWithFlags(&s1, cudaStreamNonBlocking);
    cudaEventCreateWithFlags(&ev_fork, cudaEventDisableTiming);
    cudaEventCreateWithFlags(&ev_join, cudaEventDisableTiming);

    // fork: GEMM on s1
    cudaEventRecord(ev_fork, 0);
    cudaStreamWaitEvent(s1, ev_fork, 0);
    gemm_tf32_kernel<<<(N_NODES + 127) / 128, 256, 0, s1>>>(x, W);
    cudaEventRecord(ev_join, s1);

    // CSR build on main stream (independent of GEMM)
    hist_kernel<<<(N_EDGES / 4 + 255) / 256, 256>>>(edst);
    scan_fused_kernel<<<N_SCAN_BLOCKS, SCAN_BLOCK>>>();
    place_kernel<<<(N_EDGES / 4 + 255) / 256, 256>>>(esrc, edst, ew);

    // join: pull needs both g_supph (s1) and CSR (main)
    cudaStreamWaitEvent(0, ev_join, 0);
    long long pull_threads = (long long)N_NODES * 16;
    pull_kernel<<<(int)((pull_threads + 255) / 256), 256>>>(b, out);
}